// round 6
// baseline (speedup 1.0000x reference)
#include <cuda_runtime.h>
#include <cuda_bf16.h>
#include <cstdint>

// Problem constants.
#define N_A   50000
#define N_B   100000
#define MAXNB 6
#define FA    133
#define FB    147
#define HID   600
#define KOUT  733
#define KP_I  160            // init K pad (147 -> 160, 5 steps)
#define KP_H  608            // hop  K pad (600 -> 608, 19 steps)
#define KP_O  736            // out  K pad (733 -> 736, 23 steps)
#define NBP   100096         // 782*128
#define NAP   50048          // 391*128

// Scratch (__device__ globals; no dynamic allocation allowed).
__device__ float g_inp[N_B * HID];
__device__ float g_msgbuf[2][N_B * HID];
__device__ float g_amsg[N_A * HID];
__device__ __nv_bfloat16 g_Ahi[(size_t)NBP * KP_O];   // reused for all three A's (max pad)
__device__ __nv_bfloat16 g_Alo[(size_t)NBP * KP_O];
__device__ __nv_bfloat16 g_WiT_hi[640 * KP_I], g_WiT_lo[640 * KP_I];
__device__ __nv_bfloat16 g_WhT_hi[640 * KP_H], g_WhT_lo[640 * KP_H];
__device__ __nv_bfloat16 g_WoT_hi[640 * KP_O], g_WoT_lo[640 * KP_O];

// ---------------------------------------------------------------------------
// Helpers (sm_80-era PTX: safe on compute_100 target).
// ---------------------------------------------------------------------------
__device__ __forceinline__ uint32_t smem_u32(const void* p) {
    uint32_t a;
    asm("{ .reg .u64 t; cvta.to.shared.u64 t, %1; cvt.u32.u64 %0, t; }" : "=r"(a) : "l"(p));
    return a;
}
__device__ __forceinline__ void cp16(uint32_t dst, const void* src) {
    asm volatile("cp.async.cg.shared.global [%0], [%1], 16;"
                 :: "r"(dst), "l"(__cvta_generic_to_global(src)));
}
__device__ __forceinline__ void ldsm4(uint32_t* r, uint32_t addr) {
    asm volatile("ldmatrix.sync.aligned.m8n8.x4.shared.b16 {%0,%1,%2,%3}, [%4];"
                 : "=r"(r[0]), "=r"(r[1]), "=r"(r[2]), "=r"(r[3]) : "r"(addr));
}
__device__ __forceinline__ void mma16816(float* d, const uint32_t* a, uint32_t b0, uint32_t b1) {
    asm volatile("mma.sync.aligned.m16n8k16.row.col.f32.bf16.bf16.f32 "
                 "{%0,%1,%2,%3},{%4,%5,%6,%7},{%8,%9},{%0,%1,%2,%3};"
                 : "+f"(d[0]), "+f"(d[1]), "+f"(d[2]), "+f"(d[3])
                 : "r"(a[0]), "r"(a[1]), "r"(a[2]), "r"(a[3]), "r"(b0), "r"(b1));
}

// ---------------------------------------------------------------------------
// Weight prep: WT_{hi,lo}[n][k] = split(W[k][n]); W is [K x HID], padded.
// ---------------------------------------------------------------------------
__global__ __launch_bounds__(256) void k_prepW(const float* __restrict__ W, int K, int kpad,
                                               __nv_bfloat16* __restrict__ hi,
                                               __nv_bfloat16* __restrict__ lo) {
    int i = blockIdx.x * blockDim.x + threadIdx.x;
    if (i >= 640 * kpad) return;
    int n = i / kpad, k = i - n * kpad;
    float x = (k < K && n < HID) ? W[k * HID + n] : 0.f;
    __nv_bfloat16 h = __float2bfloat16(x);
    hi[i] = h;
    lo[i] = __float2bfloat16(x - __bfloat162float(h));
}

// ---------------------------------------------------------------------------
// A prep for init: f_bonds [N_B x 147] -> bf16 hi/lo [NBP x 160].
// ---------------------------------------------------------------------------
__global__ __launch_bounds__(256) void k_prepFB(const float* __restrict__ fb) {
    int i = blockIdx.x * blockDim.x + threadIdx.x;
    if (i >= NBP * KP_I) return;
    int b = i / KP_I, k = i - b * KP_I;
    float x = (b < N_B && k < FB) ? fb[b * FB + k] : 0.f;
    __nv_bfloat16 h = __float2bfloat16(x);
    g_Ahi[i] = h;
    g_Alo[i] = __float2bfloat16(x - __bfloat162float(h));
}

// ---------------------------------------------------------------------------
// A prep per hop: A[b] = amsg[b2a[b]] - msg[b2revb[b]] -> bf16 hi/lo [NBP x 608].
// ---------------------------------------------------------------------------
__global__ __launch_bounds__(256) void k_prepA(const int* __restrict__ b2a,
                                               const int* __restrict__ b2revb,
                                               int cur) {
    const int t = blockIdx.x * blockDim.x + threadIdx.x;
    const int tot = NBP * (KP_H / 4);
    if (t >= tot) return;
    const int b = t / (KP_H / 4), c4 = t - b * (KP_H / 4);
    float4 x = make_float4(0.f, 0.f, 0.f, 0.f);
    if (b < N_B && c4 < HID / 4) {
        const int ia = b2a[b], ib = b2revb[b];
        const float4 va = *((const float4*)g_amsg + (size_t)ia * (HID / 4) + c4);
        const float4 vb = *((const float4*)g_msgbuf[cur] + (size_t)ib * (HID / 4) + c4);
        x = make_float4(va.x - vb.x, va.y - vb.y, va.z - vb.z, va.w - vb.w);
    }
    union { __nv_bfloat16 h[4]; uint2 u; } hi, lo;
    float v[4] = {x.x, x.y, x.z, x.w};
#pragma unroll
    for (int j = 0; j < 4; j++) {
        __nv_bfloat16 h = __float2bfloat16(v[j]);
        hi.h[j] = h;
        lo.h[j] = __float2bfloat16(v[j] - __bfloat162float(h));
    }
    const size_t off = (size_t)b * KP_H + c4 * 4;
    *(uint2*)(g_Ahi + off) = hi.u;
    *(uint2*)(g_Alo + off) = lo.u;
}

// ---------------------------------------------------------------------------
// A prep for output: [f_atoms | amsg] -> bf16 hi/lo [NAP x 736].
// ---------------------------------------------------------------------------
__global__ __launch_bounds__(256) void k_prepAO(const float* __restrict__ fa) {
    int i = blockIdx.x * blockDim.x + threadIdx.x;
    if (i >= NAP * KP_O) return;
    int r = i / KP_O, k = i - r * KP_O;
    float x = 0.f;
    if (r < N_A && k < KOUT)
        x = (k < FA) ? fa[r * FA + k] : g_amsg[(size_t)r * HID + (k - FA)];
    __nv_bfloat16 h = __float2bfloat16(x);
    g_Ahi[i] = h;
    g_Alo[i] = __float2bfloat16(x - __bfloat162float(h));
}

// ---------------------------------------------------------------------------
// Generic GEMM via mma.sync, bf16 hi/lo 3-pass, fp32 accum.
// CTA tile 128x128, 4 warps (2Mx2N), warp tile 64x64, K step 32,
// cp.async double-buffered, smem rows padded to 80B.
// Epilogue modes: 0: out0=D, out1=relu(D)      (init)
//                 1: out1=relu(add[r]+D)       (hop)
//                 2: out1=relu(D + bias[col])  (out)
// ---------------------------------------------------------------------------
#define ROWB   80
#define TILEB  10240
#define STAGEB 40960
#define SMEM_MMA (2 * STAGEB)

__global__ __launch_bounds__(128, 2) void k_mma(const __nv_bfloat16* __restrict__ Ah,
                                                const __nv_bfloat16* __restrict__ Al,
                                                const __nv_bfloat16* __restrict__ Bh,
                                                const __nv_bfloat16* __restrict__ Bl,
                                                int kpad, int kSteps, int Mlim,
                                                float* __restrict__ out0,
                                                float* __restrict__ out1,
                                                const float* __restrict__ aux,
                                                int mode) {
    extern __shared__ __align__(128) char smem[];
    const uint32_t sb = smem_u32(smem);
    const int tid = threadIdx.x, wid = tid >> 5, lane = tid & 31;
    const int bm = blockIdx.y, bn = blockIdx.x;
    const int wm = wid & 1, wn = wid >> 1;          // 2x2 warp grid, warp tile 64x64

    const __nv_bfloat16* __restrict__ gAh = Ah + (size_t)bm * 128 * kpad;
    const __nv_bfloat16* __restrict__ gAl = Al + (size_t)bm * 128 * kpad;
    const __nv_bfloat16* __restrict__ gBh = Bh + (size_t)bn * 128 * kpad;
    const __nv_bfloat16* __restrict__ gBl = Bl + (size_t)bn * 128 * kpad;

    auto load_stage = [&](int kc, int s) {
        const int k0 = kc * 32;
        const uint32_t base = sb + s * STAGEB;
        for (int i = tid; i < 512; i += 128) {
            const int r = i >> 2, q = i & 3;
            const uint32_t d = base + r * ROWB + q * 16;
            const size_t  g = (size_t)r * kpad + k0 + q * 8;
            cp16(d,             gAh + g);
            cp16(d + TILEB,     gAl + g);
            cp16(d + 2 * TILEB, gBh + g);
            cp16(d + 3 * TILEB, gBl + g);
        }
        asm volatile("cp.async.commit_group;" ::: "memory");
    };

    float acc[4][8][4];
#pragma unroll
    for (int i = 0; i < 4; i++)
#pragma unroll
        for (int j = 0; j < 8; j++)
#pragma unroll
            for (int q = 0; q < 4; q++) acc[i][j][q] = 0.f;

    load_stage(0, 0);
    const int lane16 = lane & 15, laneHi = lane >> 4;

    for (int kc = 0; kc < kSteps; kc++) {
        const int s = kc & 1;
        if (kc + 1 < kSteps) {
            load_stage(kc + 1, s ^ 1);
            asm volatile("cp.async.wait_group 1;" ::: "memory");
        } else {
            asm volatile("cp.async.wait_group 0;" ::: "memory");
        }
        __syncthreads();
        const uint32_t base = sb + s * STAGEB;
#pragma unroll
        for (int kk = 0; kk < 2; kk++) {
            const uint32_t kb = (kk * 16 + laneHi * 8) * 2;
            uint32_t ah[4][4], bh[4][4];
            // Pass 1: Ah x Bh
#pragma unroll
            for (int mi = 0; mi < 4; mi++)
                ldsm4(ah[mi], base + (wm * 64 + mi * 16 + lane16) * ROWB + kb);
#pragma unroll
            for (int bj = 0; bj < 4; bj++)
                ldsm4(bh[bj], base + 2 * TILEB + (wn * 64 + bj * 16 + lane16) * ROWB + kb);
#pragma unroll
            for (int mi = 0; mi < 4; mi++)
#pragma unroll
                for (int nj = 0; nj < 8; nj++)
                    mma16816(acc[mi][nj], ah[mi], bh[nj >> 1][nj & 1], bh[nj >> 1][(nj & 1) + 2]);
            // Pass 2: Al x Bh (reuse bh, overwrite nothing live except load al)
            {
                uint32_t al[4][4];
#pragma unroll
                for (int mi = 0; mi < 4; mi++)
                    ldsm4(al[mi], base + TILEB + (wm * 64 + mi * 16 + lane16) * ROWB + kb);
#pragma unroll
                for (int mi = 0; mi < 4; mi++)
#pragma unroll
                    for (int nj = 0; nj < 8; nj++)
                        mma16816(acc[mi][nj], al[mi], bh[nj >> 1][nj & 1], bh[nj >> 1][(nj & 1) + 2]);
            }
            // Pass 3: Ah x Bl (reuse ah, load bl into bh's registers)
            {
                uint32_t bl[4][4];
#pragma unroll
                for (int bj = 0; bj < 4; bj++)
                    ldsm4(bl[bj], base + 3 * TILEB + (wn * 64 + bj * 16 + lane16) * ROWB + kb);
#pragma unroll
                for (int mi = 0; mi < 4; mi++)
#pragma unroll
                    for (int nj = 0; nj < 8; nj++)
                        mma16816(acc[mi][nj], ah[mi], bl[nj >> 1][nj & 1], bl[nj >> 1][(nj & 1) + 2]);
            }
        }
        __syncthreads();
    }

    // Epilogue.
    const int mBase = bm * 128 + wm * 64;
    const int nBase = bn * 128 + wn * 64;
#pragma unroll
    for (int mi = 0; mi < 4; mi++) {
#pragma unroll
        for (int nj = 0; nj < 8; nj++) {
            const int n0 = nBase + nj * 8;
            if (n0 >= HID) continue;
            const int col = n0 + (lane & 3) * 2;
            const int rr[2] = {mBase + mi * 16 + (lane >> 2), mBase + mi * 16 + (lane >> 2) + 8};
#pragma unroll
            for (int h = 0; h < 2; h++) {
                const int r = rr[h];
                if (r >= Mlim) continue;
                const float d0 = acc[mi][nj][2 * h], d1 = acc[mi][nj][2 * h + 1];
                const size_t o = (size_t)r * HID + col;
                if (mode == 0) {
                    *(float2*)(out0 + o) = make_float2(d0, d1);
                    *(float2*)(out1 + o) = make_float2(fmaxf(d0, 0.f), fmaxf(d1, 0.f));
                } else if (mode == 1) {
                    const float2 p = *(const float2*)(aux + o);
                    *(float2*)(out1 + o) = make_float2(fmaxf(p.x + d0, 0.f), fmaxf(p.y + d1, 0.f));
                } else {
                    const float2 b = *(const float2*)(aux + col);
                    *(float2*)(out1 + o) = make_float2(fmaxf(d0 + b.x, 0.f), fmaxf(d1 + b.y, 0.f));
                }
            }
        }
    }
}

// ---------------------------------------------------------------------------
// Gather-sum: amsg[a] = sum_j msg[a2b[a][j]]  (float4).
// ---------------------------------------------------------------------------
__global__ __launch_bounds__(256) void k_gather(const int* __restrict__ a2b, int cur) {
    const int tid = blockIdx.x * blockDim.x + threadIdx.x;
    const int total = N_A * (HID / 4);
    if (tid >= total) return;
    const int a  = tid / (HID / 4);
    const int c4 = tid - a * (HID / 4);
    const float* __restrict__ msg = g_msgbuf[cur];
    const int* __restrict__ idx = a2b + a * MAXNB;
    float4 s = make_float4(0.f, 0.f, 0.f, 0.f);
#pragma unroll
    for (int j = 0; j < MAXNB; j++) {
        const float4 v = *(const float4*)(msg + (size_t)idx[j] * HID + c4 * 4);
        s.x += v.x; s.y += v.y; s.z += v.z; s.w += v.w;
    }
    *((float4*)g_amsg + tid) = s;
}

// ---------------------------------------------------------------------------
// Launch
// ---------------------------------------------------------------------------
extern "C" void kernel_launch(void* const* d_in, const int* in_sizes, int n_in,
                              void* d_out, int out_size) {
    const float* f_atoms = (const float*)d_in[0];
    const float* f_bonds = (const float*)d_in[1];
    const int*   a2b     = (const int*)d_in[2];
    const int*   b2a     = (const int*)d_in[3];
    const int*   b2revb  = (const int*)d_in[4];
    const float* W_i     = (const float*)d_in[5];
    const float* W_h     = (const float*)d_in[6];
    const float* W_o     = (const float*)d_in[7];
    const float* b_o     = (const float*)d_in[8];
    float* out = (float*)d_out;

    cudaFuncSetAttribute(k_mma, cudaFuncAttributeMaxDynamicSharedMemorySize, SMEM_MMA);

    static void *pAhi = nullptr, *pAlo, *pWiH, *pWiL, *pWhH, *pWhL, *pWoH, *pWoL,
                *pInp, *pMsg0, *pMsg1;
    if (!pAhi) {
        cudaGetSymbolAddress(&pAhi, g_Ahi);    cudaGetSymbolAddress(&pAlo, g_Alo);
        cudaGetSymbolAddress(&pWiH, g_WiT_hi); cudaGetSymbolAddress(&pWiL, g_WiT_lo);
        cudaGetSymbolAddress(&pWhH, g_WhT_hi); cudaGetSymbolAddress(&pWhL, g_WhT_lo);
        cudaGetSymbolAddress(&pWoH, g_WoT_hi); cudaGetSymbolAddress(&pWoL, g_WoT_lo);
        cudaGetSymbolAddress(&pInp, g_inp);
        cudaGetSymbolAddress(&pMsg0, g_msgbuf);
        pMsg1 = (char*)pMsg0 + sizeof(float) * (size_t)N_B * HID;
    }
    const __nv_bfloat16* Ahi = (const __nv_bfloat16*)pAhi;
    const __nv_bfloat16* Alo = (const __nv_bfloat16*)pAlo;
    float* inp  = (float*)pInp;
    float* msgb[2] = {(float*)pMsg0, (float*)pMsg1};

    dim3 blk(256), blkM(128);
    dim3 gBond(5, NBP / 128);
    dim3 gAtom(5, NAP / 128);
    const int gathBlocks  = (N_A * (HID / 4) + 255) / 256;
    const int prepABlocks = (NBP * (KP_H / 4) + 255) / 256;

    // Weight preps (small).
    k_prepW<<<(640 * KP_I + 255) / 256, blk>>>(W_i, FB,   KP_I, (__nv_bfloat16*)pWiH, (__nv_bfloat16*)pWiL);
    k_prepW<<<(640 * KP_H + 255) / 256, blk>>>(W_h, HID,  KP_H, (__nv_bfloat16*)pWhH, (__nv_bfloat16*)pWhL);
    k_prepW<<<(640 * KP_O + 255) / 256, blk>>>(W_o, KOUT, KP_O, (__nv_bfloat16*)pWoH, (__nv_bfloat16*)pWoL);

    // Init GEMM: inp = f_bonds @ W_i ; msg0 = relu(inp)
    k_prepFB<<<(NBP * KP_I + 255) / 256, blk>>>(f_bonds);
    k_mma<<<gBond, blkM, SMEM_MMA>>>(Ahi, Alo, (const __nv_bfloat16*)pWiH, (const __nv_bfloat16*)pWiL,
                                     KP_I, KP_I / 32, N_B, inp, msgb[0], nullptr, 0);

    int cur = 0;
    for (int d = 0; d < 5; d++) {
        k_gather<<<gathBlocks, blk>>>(a2b, cur);
        k_prepA<<<prepABlocks, blk>>>(b2a, b2revb, cur);
        k_mma<<<gBond, blkM, SMEM_MMA>>>(Ahi, Alo, (const __nv_bfloat16*)pWhH, (const __nv_bfloat16*)pWhL,
                                         KP_H, KP_H / 32, N_B, nullptr, msgb[cur ^ 1], inp, 1);
        cur ^= 1;
    }
    k_gather<<<gathBlocks, blk>>>(a2b, cur);

    // Output GEMM: out = relu([f_atoms | amsg] @ W_o + b_o)
    k_prepAO<<<(NAP * KP_O + 255) / 256, blk>>>(f_atoms);
    k_mma<<<gAtom, blkM, SMEM_MMA>>>(Ahi, Alo, (const __nv_bfloat16*)pWoH, (const __nv_bfloat16*)pWoL,
                                     KP_O, KP_O / 32, N_A, nullptr, out, b_o, 2);
}

// round 7
// speedup vs baseline: 1.1580x; 1.1580x over previous
#include <cuda_runtime.h>
#include <cuda_bf16.h>
#include <cstdint>

// Problem constants.
#define N_A   50000
#define N_B   100000
#define MAXNB 6
#define FA    133
#define FB    147
#define HID   600
#define KOUT  733
#define KP_I  160            // init K pad (147 -> 160, 5 steps)
#define KP_H  608            // hop  K pad (600 -> 608, 19 steps)
#define KP_O  736            // out  K pad (733 -> 736, 23 steps)
#define NBP   100096         // 782*128
#define NAP   50048          // 391*128

// Scratch (__device__ globals; no dynamic allocation allowed).
__device__ float g_inp[N_B * HID];
__device__ float g_msgbuf[2][N_B * HID];
__device__ float g_amsg[N_A * HID];
__device__ __nv_bfloat16 g_Ahi[(size_t)NBP * KP_O];   // reused for all three A's (max pad)
__device__ __nv_bfloat16 g_Alo[(size_t)NBP * KP_O];
__device__ __nv_bfloat16 g_WiT_hi[640 * KP_I], g_WiT_lo[640 * KP_I];
__device__ __nv_bfloat16 g_WhT_hi[640 * KP_H], g_WhT_lo[640 * KP_H];
__device__ __nv_bfloat16 g_WoT_hi[640 * KP_O], g_WoT_lo[640 * KP_O];

// ---------------------------------------------------------------------------
// Helpers (sm_80-era PTX: safe on compute_100 target).
// ---------------------------------------------------------------------------
__device__ __forceinline__ uint32_t smem_u32(const void* p) {
    uint32_t a;
    asm("{ .reg .u64 t; cvta.to.shared.u64 t, %1; cvt.u32.u64 %0, t; }" : "=r"(a) : "l"(p));
    return a;
}
__device__ __forceinline__ void cp16(uint32_t dst, const void* src) {
    asm volatile("cp.async.cg.shared.global [%0], [%1], 16;"
                 :: "r"(dst), "l"(__cvta_generic_to_global(src)));
}
__device__ __forceinline__ void ldsm4(uint32_t* r, uint32_t addr) {
    asm volatile("ldmatrix.sync.aligned.m8n8.x4.shared.b16 {%0,%1,%2,%3}, [%4];"
                 : "=r"(r[0]), "=r"(r[1]), "=r"(r[2]), "=r"(r[3]) : "r"(addr));
}
__device__ __forceinline__ void mma16816(float* d, const uint32_t* a, uint32_t b0, uint32_t b1) {
    asm volatile("mma.sync.aligned.m16n8k16.row.col.f32.bf16.bf16.f32 "
                 "{%0,%1,%2,%3},{%4,%5,%6,%7},{%8,%9},{%0,%1,%2,%3};"
                 : "+f"(d[0]), "+f"(d[1]), "+f"(d[2]), "+f"(d[3])
                 : "r"(a[0]), "r"(a[1]), "r"(a[2]), "r"(a[3]), "r"(b0), "r"(b1));
}

// ---------------------------------------------------------------------------
// Weight prep: WT_{hi,lo}[n][k] = split(W[k][n]); W is [K x HID], padded.
// ---------------------------------------------------------------------------
__global__ __launch_bounds__(256) void k_prepW(const float* __restrict__ W, int K, int kpad,
                                               __nv_bfloat16* __restrict__ hi,
                                               __nv_bfloat16* __restrict__ lo) {
    int i = blockIdx.x * blockDim.x + threadIdx.x;
    if (i >= 640 * kpad) return;
    int n = i / kpad, k = i - n * kpad;
    float x = (k < K && n < HID) ? W[k * HID + n] : 0.f;
    __nv_bfloat16 h = __float2bfloat16(x);
    hi[i] = h;
    lo[i] = __float2bfloat16(x - __bfloat162float(h));
}

// ---------------------------------------------------------------------------
// A prep for init: f_bonds [N_B x 147] -> bf16 hi/lo [NBP x 160].
// ---------------------------------------------------------------------------
__global__ __launch_bounds__(256) void k_prepFB(const float* __restrict__ fb) {
    int i = blockIdx.x * blockDim.x + threadIdx.x;
    if (i >= NBP * KP_I) return;
    int b = i / KP_I, k = i - b * KP_I;
    float x = (b < N_B && k < FB) ? fb[b * FB + k] : 0.f;
    __nv_bfloat16 h = __float2bfloat16(x);
    g_Ahi[i] = h;
    g_Alo[i] = __float2bfloat16(x - __bfloat162float(h));
}

// ---------------------------------------------------------------------------
// A prep per hop: A[b] = amsg[b2a[b]] - msg[b2revb[b]] -> bf16 hi/lo [NBP x 608].
// ---------------------------------------------------------------------------
__global__ __launch_bounds__(256) void k_prepA(const int* __restrict__ b2a,
                                               const int* __restrict__ b2revb,
                                               int cur) {
    const int t = blockIdx.x * blockDim.x + threadIdx.x;
    const int tot = NBP * (KP_H / 4);
    if (t >= tot) return;
    const int b = t / (KP_H / 4), c4 = t - b * (KP_H / 4);
    float4 x = make_float4(0.f, 0.f, 0.f, 0.f);
    if (b < N_B && c4 < HID / 4) {
        const int ia = b2a[b], ib = b2revb[b];
        const float4 va = *((const float4*)g_amsg + (size_t)ia * (HID / 4) + c4);
        const float4 vb = *((const float4*)g_msgbuf[cur] + (size_t)ib * (HID / 4) + c4);
        x = make_float4(va.x - vb.x, va.y - vb.y, va.z - vb.z, va.w - vb.w);
    }
    union { __nv_bfloat16 h[4]; uint2 u; } hi, lo;
    float v[4] = {x.x, x.y, x.z, x.w};
#pragma unroll
    for (int j = 0; j < 4; j++) {
        __nv_bfloat16 h = __float2bfloat16(v[j]);
        hi.h[j] = h;
        lo.h[j] = __float2bfloat16(v[j] - __bfloat162float(h));
    }
    const size_t off = (size_t)b * KP_H + c4 * 4;
    *(uint2*)(g_Ahi + off) = hi.u;
    *(uint2*)(g_Alo + off) = lo.u;
}

// ---------------------------------------------------------------------------
// A prep for output: [f_atoms | amsg] -> bf16 hi/lo [NAP x 736].
// ---------------------------------------------------------------------------
__global__ __launch_bounds__(256) void k_prepAO(const float* __restrict__ fa) {
    int i = blockIdx.x * blockDim.x + threadIdx.x;
    if (i >= NAP * KP_O) return;
    int r = i / KP_O, k = i - r * KP_O;
    float x = 0.f;
    if (r < N_A && k < KOUT)
        x = (k < FA) ? fa[r * FA + k] : g_amsg[(size_t)r * HID + (k - FA)];
    __nv_bfloat16 h = __float2bfloat16(x);
    g_Ahi[i] = h;
    g_Alo[i] = __float2bfloat16(x - __bfloat162float(h));
}

// ---------------------------------------------------------------------------
// Generic GEMM via mma.sync, bf16 hi/lo 3-pass, fp32 accum.
// CTA tile 128x128, 8 warps (2Mx4N), warp tile 64x32, K step 32,
// cp.async double-buffered, smem rows padded to 80B.  (Proven R5 config.)
// Epilogue modes: 0: out0=D, out1=relu(D)      (init)
//                 1: out1=relu(add[r]+D)       (hop)
//                 2: out1=relu(D + bias[col])  (out)
// ---------------------------------------------------------------------------
#define ROWB   80
#define TILEB  10240
#define STAGEB 40960
#define SMEM_MMA (2 * STAGEB)

__global__ __launch_bounds__(256) void k_mma(const __nv_bfloat16* __restrict__ Ah,
                                             const __nv_bfloat16* __restrict__ Al,
                                             const __nv_bfloat16* __restrict__ Bh,
                                             const __nv_bfloat16* __restrict__ Bl,
                                             int kpad, int kSteps, int Mlim,
                                             float* __restrict__ out0,
                                             float* __restrict__ out1,
                                             const float* __restrict__ aux,
                                             int mode) {
    extern __shared__ __align__(128) char smem[];
    const uint32_t sb = smem_u32(smem);
    const int tid = threadIdx.x, wid = tid >> 5, lane = tid & 31;
    const int bm = blockIdx.y, bn = blockIdx.x;
    const int wm = wid & 1, wn = wid >> 1;

    const __nv_bfloat16* __restrict__ gAh = Ah + (size_t)bm * 128 * kpad;
    const __nv_bfloat16* __restrict__ gAl = Al + (size_t)bm * 128 * kpad;
    const __nv_bfloat16* __restrict__ gBh = Bh + (size_t)bn * 128 * kpad;
    const __nv_bfloat16* __restrict__ gBl = Bl + (size_t)bn * 128 * kpad;

    auto load_stage = [&](int kc, int s) {
        const int k0 = kc * 32;
        const uint32_t base = sb + s * STAGEB;
        for (int i = tid; i < 512; i += 256) {
            const int r = i >> 2, q = i & 3;
            const uint32_t d = base + r * ROWB + q * 16;
            const size_t  g = (size_t)r * kpad + k0 + q * 8;
            cp16(d,             gAh + g);
            cp16(d + TILEB,     gAl + g);
            cp16(d + 2 * TILEB, gBh + g);
            cp16(d + 3 * TILEB, gBl + g);
        }
        asm volatile("cp.async.commit_group;" ::: "memory");
    };

    float acc[4][4][4];
#pragma unroll
    for (int i = 0; i < 4; i++)
#pragma unroll
        for (int j = 0; j < 4; j++)
#pragma unroll
            for (int q = 0; q < 4; q++) acc[i][j][q] = 0.f;

    load_stage(0, 0);
    const int lane16 = lane & 15, laneHi = lane >> 4;

    for (int kc = 0; kc < kSteps; kc++) {
        const int s = kc & 1;
        if (kc + 1 < kSteps) {
            load_stage(kc + 1, s ^ 1);
            asm volatile("cp.async.wait_group 1;" ::: "memory");
        } else {
            asm volatile("cp.async.wait_group 0;" ::: "memory");
        }
        __syncthreads();
        const uint32_t base = sb + s * STAGEB;
#pragma unroll
        for (int kk = 0; kk < 2; kk++) {
            const uint32_t kb = (kk * 16 + laneHi * 8) * 2;
            uint32_t ah[4][4], al[4][4], bhf[2][4], blf[2][4];
#pragma unroll
            for (int mi = 0; mi < 4; mi++) {
                const uint32_t ra = base + (wm * 64 + mi * 16 + lane16) * ROWB + kb;
                ldsm4(ah[mi], ra);
                ldsm4(al[mi], ra + TILEB);
            }
#pragma unroll
            for (int bj = 0; bj < 2; bj++) {
                const uint32_t rb = base + 2 * TILEB + (wn * 32 + bj * 16 + lane16) * ROWB + kb;
                ldsm4(bhf[bj], rb);
                ldsm4(blf[bj], rb + TILEB);
            }
#pragma unroll
            for (int mi = 0; mi < 4; mi++)
#pragma unroll
                for (int nj = 0; nj < 4; nj++) {
                    const uint32_t b0h = bhf[nj >> 1][nj & 1], b1h = bhf[nj >> 1][(nj & 1) + 2];
                    const uint32_t b0l = blf[nj >> 1][nj & 1], b1l = blf[nj >> 1][(nj & 1) + 2];
                    mma16816(acc[mi][nj], ah[mi], b0h, b1h);
                    mma16816(acc[mi][nj], ah[mi], b0l, b1l);
                    mma16816(acc[mi][nj], al[mi], b0h, b1h);
                }
        }
        __syncthreads();
    }

    // Epilogue.
    const int mBase = bm * 128 + wm * 64;
    const int nBase = bn * 128 + wn * 32;
#pragma unroll
    for (int mi = 0; mi < 4; mi++) {
#pragma unroll
        for (int nj = 0; nj < 4; nj++) {
            const int n0 = nBase + nj * 8;
            if (n0 >= HID) continue;
            const int col = n0 + (lane & 3) * 2;
            const int rr[2] = {mBase + mi * 16 + (lane >> 2), mBase + mi * 16 + (lane >> 2) + 8};
#pragma unroll
            for (int h = 0; h < 2; h++) {
                const int r = rr[h];
                if (r >= Mlim) continue;
                const float d0 = acc[mi][nj][2 * h], d1 = acc[mi][nj][2 * h + 1];
                const size_t o = (size_t)r * HID + col;
                if (mode == 0) {
                    *(float2*)(out0 + o) = make_float2(d0, d1);
                    *(float2*)(out1 + o) = make_float2(fmaxf(d0, 0.f), fmaxf(d1, 0.f));
                } else if (mode == 1) {
                    const float2 p = *(const float2*)(aux + o);
                    *(float2*)(out1 + o) = make_float2(fmaxf(p.x + d0, 0.f), fmaxf(p.y + d1, 0.f));
                } else {
                    const float2 b = *(const float2*)(aux + col);
                    *(float2*)(out1 + o) = make_float2(fmaxf(d0 + b.x, 0.f), fmaxf(d1 + b.y, 0.f));
                }
            }
        }
    }
}

// ---------------------------------------------------------------------------
// Gather-sum: amsg[a] = sum_j msg[a2b[a][j]]  (float4).
// ---------------------------------------------------------------------------
__global__ __launch_bounds__(256) void k_gather(const int* __restrict__ a2b, int cur) {
    const int tid = blockIdx.x * blockDim.x + threadIdx.x;
    const int total = N_A * (HID / 4);
    if (tid >= total) return;
    const int a  = tid / (HID / 4);
    const int c4 = tid - a * (HID / 4);
    const float* __restrict__ msg = g_msgbuf[cur];
    const int* __restrict__ idx = a2b + a * MAXNB;
    float4 s = make_float4(0.f, 0.f, 0.f, 0.f);
#pragma unroll
    for (int j = 0; j < MAXNB; j++) {
        const float4 v = *(const float4*)(msg + (size_t)idx[j] * HID + c4 * 4);
        s.x += v.x; s.y += v.y; s.z += v.z; s.w += v.w;
    }
    *((float4*)g_amsg + tid) = s;
}

// ---------------------------------------------------------------------------
// Launch
// ---------------------------------------------------------------------------
extern "C" void kernel_launch(void* const* d_in, const int* in_sizes, int n_in,
                              void* d_out, int out_size) {
    const float* f_atoms = (const float*)d_in[0];
    const float* f_bonds = (const float*)d_in[1];
    const int*   a2b     = (const int*)d_in[2];
    const int*   b2a     = (const int*)d_in[3];
    const int*   b2revb  = (const int*)d_in[4];
    const float* W_i     = (const float*)d_in[5];
    const float* W_h     = (const float*)d_in[6];
    const float* W_o     = (const float*)d_in[7];
    const float* b_o     = (const float*)d_in[8];
    float* out = (float*)d_out;

    cudaFuncSetAttribute(k_mma, cudaFuncAttributeMaxDynamicSharedMemorySize, SMEM_MMA);

    static void *pAhi = nullptr, *pAlo, *pWiH, *pWiL, *pWhH, *pWhL, *pWoH, *pWoL,
                *pInp, *pMsg0, *pMsg1;
    if (!pAhi) {
        cudaGetSymbolAddress(&pAhi, g_Ahi);    cudaGetSymbolAddress(&pAlo, g_Alo);
        cudaGetSymbolAddress(&pWiH, g_WiT_hi); cudaGetSymbolAddress(&pWiL, g_WiT_lo);
        cudaGetSymbolAddress(&pWhH, g_WhT_hi); cudaGetSymbolAddress(&pWhL, g_WhT_lo);
        cudaGetSymbolAddress(&pWoH, g_WoT_hi); cudaGetSymbolAddress(&pWoL, g_WoT_lo);
        cudaGetSymbolAddress(&pInp, g_inp);
        cudaGetSymbolAddress(&pMsg0, g_msgbuf);
        pMsg1 = (char*)pMsg0 + sizeof(float) * (size_t)N_B * HID;
    }
    const __nv_bfloat16* Ahi = (const __nv_bfloat16*)pAhi;
    const __nv_bfloat16* Alo = (const __nv_bfloat16*)pAlo;
    float* inp  = (float*)pInp;
    float* msgb[2] = {(float*)pMsg0, (float*)pMsg1};

    dim3 blk(256);
    dim3 gBond(5, NBP / 128);
    dim3 gAtom(5, NAP / 128);
    const int gathBlocks  = (N_A * (HID / 4) + 255) / 256;
    const int prepABlocks = (NBP * (KP_H / 4) + 255) / 256;

    // Weight preps (small).
    k_prepW<<<(640 * KP_I + 255) / 256, blk>>>(W_i, FB,   KP_I, (__nv_bfloat16*)pWiH, (__nv_bfloat16*)pWiL);
    k_prepW<<<(640 * KP_H + 255) / 256, blk>>>(W_h, HID,  KP_H, (__nv_bfloat16*)pWhH, (__nv_bfloat16*)pWhL);
    k_prepW<<<(640 * KP_O + 255) / 256, blk>>>(W_o, KOUT, KP_O, (__nv_bfloat16*)pWoH, (__nv_bfloat16*)pWoL);

    // Init GEMM: inp = f_bonds @ W_i ; msg0 = relu(inp)
    k_prepFB<<<(NBP * KP_I + 255) / 256, blk>>>(f_bonds);
    k_mma<<<gBond, blk, SMEM_MMA>>>(Ahi, Alo, (const __nv_bfloat16*)pWiH, (const __nv_bfloat16*)pWiL,
                                    KP_I, KP_I / 32, N_B, inp, msgb[0], nullptr, 0);

    int cur = 0;
    for (int d = 0; d < 5; d++) {
        k_gather<<<gathBlocks, blk>>>(a2b, cur);
        k_prepA<<<prepABlocks, blk>>>(b2a, b2revb, cur);
        k_mma<<<gBond, blk, SMEM_MMA>>>(Ahi, Alo, (const __nv_bfloat16*)pWhH, (const __nv_bfloat16*)pWhL,
                                        KP_H, KP_H / 32, N_B, nullptr, msgb[cur ^ 1], inp, 1);
        cur ^= 1;
    }
    k_gather<<<gathBlocks, blk>>>(a2b, cur);

    // Output GEMM: out = relu([f_atoms | amsg] @ W_o + b_o)
    k_prepAO<<<(NAP * KP_O + 255) / 256, blk>>>(f_atoms);
    k_mma<<<gAtom, blk, SMEM_MMA>>>(Ahi, Alo, (const __nv_bfloat16*)pWoH, (const __nv_bfloat16*)pWoL,
                                    KP_O, KP_O / 32, N_A, nullptr, out, b_o, 2);
}